// round 10
// baseline (speedup 1.0000x reference)
#include <cuda_runtime.h>
#include <math_constants.h>

// PhiCell hysteresis scan: out_i = clamp(out_{i-1}, x_i, x_i + 1), x_i = in_i*k.
// Clamp-map composition is associative -> scan over (L,H) clamp maps.
// R10: phase1 computes per-block composites AND materializes each thread's
// within-block exclusive prefix (g_thr, L2-resident). Last finishing block
// scans the 4096 block composites (threadfence-reduction, no spinning).
// Phase2 has NO scan and NO barriers: load e, compose with block prefix, emit.

#define BLOCK 256
#define ITEMS 8
#define CHUNK (BLOCK * ITEMS)   // 2048 elements per tile
#define MAXB  4096

struct CH { float L, H; };

__device__ __forceinline__ CH ch_id() {
    CH r; r.L = -CUDART_INF_F; r.H = CUDART_INF_F; return r;
}
// compose: apply a FIRST, then b
__device__ __forceinline__ CH ch_comp(CH a, CH b) {
    CH r;
    r.L = fminf(fmaxf(a.L, b.L), b.H);
    r.H = fminf(fmaxf(a.H, b.L), b.H);
    return r;
}

__device__ float2 g_part[MAXB];
__device__ float2 g_excl[MAXB];
__device__ float2 g_thr[MAXB * BLOCK];   // per-thread exclusive prefixes (8 MB)
__device__ int    g_cnt;                 // zero-init; last block resets

__device__ __forceinline__ CH warp_incl_scan(CH v, int lane) {
#pragma unroll
    for (int off = 1; off < 32; off <<= 1) {
        float pl = __shfl_up_sync(0xffffffffu, v.L, off);
        float ph = __shfl_up_sync(0xffffffffu, v.H, off);
        if (lane >= off) { CH p; p.L = pl; p.H = ph; v = ch_comp(p, v); }
    }
    return v;
}

// exclusive composite of all lower-threadIdx threads (identity for t==0)
__device__ CH block_excl_scan(CH v) {
    __shared__ CH ws[BLOCK / 32];
    int lane = threadIdx.x & 31;
    int wid  = threadIdx.x >> 5;

    CH vi = warp_incl_scan(v, lane);
    if (lane == 31) ws[wid] = vi;
    __syncthreads();
    if (wid == 0) {
        CH w = (lane < BLOCK / 32) ? ws[lane] : ch_id();
        w = warp_incl_scan(w, lane);
        if (lane < BLOCK / 32) ws[lane] = w;
    }
    __syncthreads();
    CH wp = (wid > 0) ? ws[wid - 1] : ch_id();

    float pl = __shfl_up_sync(0xffffffffu, vi.L, 1);
    float ph = __shfl_up_sync(0xffffffffu, vi.H, 1);
    CH ve = ch_id();
    if (lane > 0) { ve.L = pl; ve.H = ph; }
    return ch_comp(wp, ve);
}

__device__ __forceinline__ void absorb(CH& c, float a) {
    float ap = a + 1.0f;
    c.L = fminf(fmaxf(c.L, a), ap);
    c.H = fminf(fmaxf(c.H, a), ap);
}

// K1: per-block composite + per-thread prefix store; last block scans composites.
__global__ void __launch_bounds__(BLOCK)
k_phase1(const float* __restrict__ in, const float* __restrict__ kw) {
    __shared__ bool s_last;
    float k = __ldg(kw);
    int bid = blockIdx.x;
    int tid = threadIdx.x;
    const float4* p = reinterpret_cast<const float4*>(in + bid * CHUNK + tid * ITEMS);

    float4 xa = __ldg(&p[0]);
    float4 xb = __ldg(&p[1]);
    CH c = ch_id();
    absorb(c, xa.x * k); absorb(c, xa.y * k);
    absorb(c, xa.z * k); absorb(c, xa.w * k);
    absorb(c, xb.x * k); absorb(c, xb.y * k);
    absorb(c, xb.z * k); absorb(c, xb.w * k);

    CH e = block_excl_scan(c);

    // materialize per-thread exclusive prefix (L2-resident for phase2)
    __stcg(&g_thr[bid * BLOCK + tid], make_float2(e.L, e.H));

    if (tid == BLOCK - 1) {
        CH t = ch_comp(e, c);
        g_part[bid] = make_float2(t.L, t.H);
        __threadfence();
        int old = atomicAdd(&g_cnt, 1);
        s_last = (old == (int)gridDim.x - 1);
    }
    __syncthreads();

    if (s_last) {
        __threadfence();                       // acquire side
        const int P = MAXB / BLOCK;            // 16
        int nb = gridDim.x;
        CH loc[P];
        CH acc = ch_id();
#pragma unroll
        for (int j = 0; j < P; j++) {
            int i = tid * P + j;
            CH x = ch_id();
            if (i < nb) { float2 f = g_part[i]; x.L = f.x; x.H = f.y; }
            acc = ch_comp(acc, x);
            loc[j] = acc;                      // local inclusive
        }
        CH te = block_excl_scan(acc);
#pragma unroll
        for (int j = 0; j < P; j++) {
            int i = tid * P + j;
            if (i < nb) {
                CH ex = (j == 0) ? te : ch_comp(te, loc[j - 1]);
                g_excl[i] = make_float2(ex.L, ex.H);
            }
        }
        if (tid == 0) g_cnt = 0;               // reset for next graph replay
    }
}

// K2: no scan, no barriers. Load e + block prefix, run recurrence, write.
__global__ void __launch_bounds__(BLOCK)
k_phase2(const float* __restrict__ in, const float* __restrict__ kw,
         const float* __restrict__ stt, float* __restrict__ out,
         int n, int out_size) {
    float k  = __ldg(kw);
    int bid  = blockIdx.x;
    int tid  = threadIdx.x;
    int base = bid * CHUNK + tid * ITEMS;
    const float4* p = reinterpret_cast<const float4*>(in + base);

    float4 xa = __ldg(&p[0]);
    float4 xb = __ldg(&p[1]);
    float2 ev  = __ldcg(&g_thr[bid * BLOCK + tid]);
    float2 be2 = __ldcg(&g_excl[bid]);

    CH be; be.L = be2.x; be.H = be2.y;
    CH e;  e.L  = ev.x;  e.H  = ev.y;
    CH my = ch_comp(be, e);

    float s0   = __ldg(stt);
    float prev = fminf(fmaxf(s0, my.L), my.H);   // = out[base-1]

    float a;
    float4 r;
    a = xa.x * k; prev = fminf(fmaxf(prev, a), a + 1.0f); r.x = prev;
    a = xa.y * k; prev = fminf(fmaxf(prev, a), a + 1.0f); r.y = prev;
    a = xa.z * k; prev = fminf(fmaxf(prev, a), a + 1.0f); r.z = prev;
    a = xa.w * k; prev = fminf(fmaxf(prev, a), a + 1.0f); r.w = prev;
    float4* o = reinterpret_cast<float4*>(out + base);
    __stcs(&o[0], r);
    a = xb.x * k; prev = fminf(fmaxf(prev, a), a + 1.0f); r.x = prev;
    a = xb.y * k; prev = fminf(fmaxf(prev, a), a + 1.0f); r.y = prev;
    a = xb.z * k; prev = fminf(fmaxf(prev, a), a + 1.0f); r.z = prev;
    a = xb.w * k; prev = fminf(fmaxf(prev, a), a + 1.0f); r.w = prev;
    __stcs(&o[1], r);

    // new_state appended after T outputs, if present
    if (base + ITEMS == n && out_size > n) out[n] = prev;
}

extern "C" void kernel_launch(void* const* d_in, const int* in_sizes, int n_in,
                              void* d_out, int out_size) {
    const float* in  = (const float*)d_in[0];   // inputs [1, T]
    const float* stt = (const float*)d_in[1];   // state  [1, 1]
    const float* kw  = (const float*)d_in[2];   // kernel [1, 1]
    float* out = (float*)d_out;

    int n  = in_sizes[0];
    int nb = n / CHUNK;                         // 2^23 / 2048 = 4096 tiles

    k_phase1<<<nb, BLOCK>>>(in, kw);
    k_phase2<<<nb, BLOCK>>>(in, kw, stt, out, n, out_size);
}